// round 1
// baseline (speedup 1.0000x reference)
#include <cuda_runtime.h>
#include <math.h>

// ---------------- problem constants ----------------
#define T_TOK   2048        // B*S
#define DM      1024
#define NH      16
#define HD      64
#define FF      4096
#define VOCAB   32000
#define SEQL    128
#define NSTEPS  12
#define LOGITS_ELEMS 65536000LL   // 2048*32000
#define ENTS_ELEMS   393216LL     // 12*2048*16

// ---------------- device scratch (no cudaMalloc allowed) ----------------
__device__ float g_h  [T_TOK*DM];
__device__ float g_lnb[T_TOK*DM];
__device__ float g_q  [T_TOK*DM];
__device__ float g_k  [T_TOK*DM];
__device__ float g_v  [T_TOK*DM];
__device__ float g_o  [T_TOK*DM];
__device__ float g_mid[T_TOK*FF];
__device__ float g_ents_scratch[NSTEPS*T_TOK*NH];
__device__ float g_cos[SEQL*32];
__device__ float g_sin[SEQL*32];

// ---------------- RoPE table ----------------
__global__ void rope_table_kernel() {
    int i = blockIdx.x * blockDim.x + threadIdx.x;
    if (i >= SEQL * 32) return;
    int s = i >> 5;
    int j = i & 31;
    // inv = 10000^(-(2j)/64)
    float inv = expf(-((2.0f * j) / 64.0f) * 9.210340371976184f); // ln(10000)
    float f = (float)s * inv;
    g_cos[i] = cosf(f);
    g_sin[i] = sinf(f);
}

// ---------------- embedding gather ----------------
__global__ void embed_kernel(const int* __restrict__ x,
                             const float* __restrict__ emb,
                             float* __restrict__ h) {
    int i = blockIdx.x * blockDim.x + threadIdx.x;     // float4 units
    if (i >= T_TOK * (DM / 4)) return;
    int row = i >> 8;               // DM/4 = 256
    int col = i & 255;
    int tok = x[row];
    reinterpret_cast<float4*>(h)[(size_t)row * 256 + col] =
        reinterpret_cast<const float4*>(emb)[(size_t)tok * 256 + col];
}

// ---------------- LayerNorm (one block per token) ----------------
__global__ void ln_kernel(const float* __restrict__ x,
                          const float* __restrict__ w,
                          const float* __restrict__ b,
                          float* __restrict__ y) {
    int t = blockIdx.x;
    int tid = threadIdx.x;
    const float4* xr = reinterpret_cast<const float4*>(x + (size_t)t * DM);
    float4 v = xr[tid];
    float s  = v.x + v.y + v.z + v.w;
    float sq = v.x*v.x + v.y*v.y + v.z*v.z + v.w*v.w;
    #pragma unroll
    for (int o = 16; o > 0; o >>= 1) {
        s  += __shfl_down_sync(0xFFFFFFFFu, s,  o);
        sq += __shfl_down_sync(0xFFFFFFFFu, sq, o);
    }
    __shared__ float ss[8], sqs[8];
    __shared__ float s_mean, s_rstd;
    int wid = tid >> 5, lane = tid & 31;
    if (lane == 0) { ss[wid] = s; sqs[wid] = sq; }
    __syncthreads();
    if (tid == 0) {
        float S = 0.f, Q = 0.f;
        #pragma unroll
        for (int i = 0; i < 8; i++) { S += ss[i]; Q += sqs[i]; }
        float m = S * (1.0f / DM);
        float var = Q * (1.0f / DM) - m * m;
        s_mean = m;
        s_rstd = rsqrtf(var + 1e-5f);
    }
    __syncthreads();
    float m = s_mean, r = s_rstd;
    float4 wv = reinterpret_cast<const float4*>(w)[tid];
    float4 bv = reinterpret_cast<const float4*>(b)[tid];
    float4 out;
    out.x = (v.x - m) * r * wv.x + bv.x;
    out.y = (v.y - m) * r * wv.y + bv.y;
    out.z = (v.z - m) * r * wv.z + bv.z;
    out.w = (v.w - m) * r * wv.w + bv.w;
    reinterpret_cast<float4*>(y + (size_t)t * DM)[tid] = out;
}

// ---------------- RoPE apply (in-place) ----------------
__global__ void rope_apply_kernel(float* __restrict__ x) {
    int i = blockIdx.x * blockDim.x + threadIdx.x;   // pair index
    if (i >= T_TOK * NH * 32) return;
    int t   = i >> 9;          // NH*32 = 512
    int rem = i & 511;
    int h   = rem >> 5;
    int j   = rem & 31;
    int s   = t & (SEQL - 1);
    float c  = g_cos[s * 32 + j];
    float sn = g_sin[s * 32 + j];
    size_t base = (size_t)t * DM + h * HD + 2 * j;
    float xr = x[base], xi = x[base + 1];
    x[base]     = xr * c - xi * sn;
    x[base + 1] = xr * sn + xi * c;
}

// ---------------- fused attention + entropy (one block per (b,h)) ----------------
#define ATTN_SMEM ((8192 + 8192 + 128*129) * 4)
__global__ void __launch_bounds__(128) attn_kernel(
    const float* __restrict__ q, const float* __restrict__ k,
    const float* __restrict__ v, float* __restrict__ o,
    float* __restrict__ ent) {
    extern __shared__ float sm[];
    float* Ks = sm;                 // 128 x 64
    float* Vs = sm + 8192;          // 128 x 64
    float* Sc = sm + 16384;         // 128 x 129 (padded)
    int bh = blockIdx.x;
    int b = bh >> 4, h = bh & 15;
    size_t rowbase = (size_t)(b * SEQL) * DM + h * HD;
    int tid = threadIdx.x;

    // cooperative load of K, V tiles (float4 units: 128 rows * 16)
    for (int i = tid; i < 2048; i += 128) {
        int r = i >> 4;
        int c = (i & 15) << 2;
        *reinterpret_cast<float4*>(&Ks[r * 64 + c]) =
            *reinterpret_cast<const float4*>(k + rowbase + (size_t)r * DM + c);
        *reinterpret_cast<float4*>(&Vs[r * 64 + c]) =
            *reinterpret_cast<const float4*>(v + rowbase + (size_t)r * DM + c);
    }
    // per-thread query row
    float qr[64];
    const float* qp = q + rowbase + (size_t)tid * DM;
    #pragma unroll
    for (int c = 0; c < 64; c += 4) {
        float4 t4 = *reinterpret_cast<const float4*>(qp + c);
        qr[c] = t4.x; qr[c+1] = t4.y; qr[c+2] = t4.z; qr[c+3] = t4.w;
    }
    __syncthreads();

    float* srow = &Sc[tid * 129];
    float mx = -1e30f;
    for (int kk = 0; kk < 128; kk++) {
        float d = 0.f;
        const float* krow = &Ks[kk * 64];
        #pragma unroll
        for (int c = 0; c < 64; c++) d += qr[c] * krow[c];
        d *= 0.125f;                      // HEAD_DIM^-0.5
        srow[kk] = d;
        mx = fmaxf(mx, d);
    }
    float l = 0.f, s1 = 0.f;
    for (int kk = 0; kk < 128; kk++) {
        float sv = srow[kk] - mx;
        float e = expf(sv);
        l  += e;
        s1 += e * sv;
        srow[kk] = e;
    }
    float invl = 1.0f / l;
    // ent = (log(l) - s1/l) * log2(e)
    ent[(size_t)(b * SEQL + tid) * NH + h] = (logf(l) - s1 * invl) * 1.44269504f;

    float acc[64];
    #pragma unroll
    for (int c = 0; c < 64; c++) acc[c] = 0.f;
    for (int kk = 0; kk < 128; kk++) {
        float p = srow[kk];
        const float* vrow = &Vs[kk * 64];
        #pragma unroll
        for (int c = 0; c < 64; c++) acc[c] += p * vrow[c];
    }
    float* op = o + rowbase + (size_t)tid * DM;
    #pragma unroll
    for (int c = 0; c < 64; c += 4) {
        float4 t4 = make_float4(acc[c]*invl, acc[c+1]*invl, acc[c+2]*invl, acc[c+3]*invl);
        *reinterpret_cast<float4*>(op + c) = t4;
    }
}

// ---------------- tiled fp32 NT GEMM: C[M,N] = A[M,K] * B[N,K]^T (+epilogue) ----------------
// EPI flags: 1 = +Cin residual, 2 = +bias, 4 = exact GELU (after bias, before residual)
#define BMt 128
#define BNt 128
#define BKt 16
template<int EPI>
__global__ void __launch_bounds__(256) sgemm_nt(
    const float* __restrict__ A, const float* __restrict__ B,
    const float* __restrict__ bias, const float* __restrict__ Cin,
    float* __restrict__ C, int M, int N, int K) {
    __shared__ float As[BKt][BMt + 4];
    __shared__ float Bs[BKt][BNt + 4];
    const int tid = threadIdx.x;
    const int tm = (tid >> 4) << 3;
    const int tn = (tid & 15) << 3;
    const int mBase = blockIdx.y * BMt;
    const int nBase = blockIdx.x * BNt;
    const float* Ab = A + (size_t)mBase * K;
    const float* Bb = B + (size_t)nBase * K;

    float acc[8][8];
    #pragma unroll
    for (int i = 0; i < 8; i++)
        #pragma unroll
        for (int j = 0; j < 8; j++) acc[i][j] = 0.f;

    const int lr = tid >> 2;          // 0..63
    const int lc = (tid & 3) << 2;    // 0,4,8,12

    for (int kt = 0; kt < K; kt += BKt) {
        #pragma unroll
        for (int half = 0; half < 2; half++) {
            int r = lr + 64 * half;
            float4 a = *reinterpret_cast<const float4*>(Ab + (size_t)r * K + kt + lc);
            As[lc + 0][r] = a.x; As[lc + 1][r] = a.y;
            As[lc + 2][r] = a.z; As[lc + 3][r] = a.w;
            float4 bv = *reinterpret_cast<const float4*>(Bb + (size_t)r * K + kt + lc);
            Bs[lc + 0][r] = bv.x; Bs[lc + 1][r] = bv.y;
            Bs[lc + 2][r] = bv.z; Bs[lc + 3][r] = bv.w;
        }
        __syncthreads();
        #pragma unroll
        for (int kk = 0; kk < BKt; kk++) {
            float ra[8], rb[8];
            #pragma unroll
            for (int i = 0; i < 8; i++) ra[i] = As[kk][tm + i];
            #pragma unroll
            for (int j = 0; j < 8; j++) rb[j] = Bs[kk][tn + j];
            #pragma unroll
            for (int i = 0; i < 8; i++)
                #pragma unroll
                for (int j = 0; j < 8; j++)
                    acc[i][j] += ra[i] * rb[j];
        }
        __syncthreads();
    }

    #pragma unroll
    for (int i = 0; i < 8; i++) {
        size_t row = (size_t)(mBase + tm + i);
        float* crow = C + row * N + nBase + tn;
        const float* cinrow = (EPI & 1) ? (Cin + row * N + nBase + tn) : nullptr;
        #pragma unroll
        for (int j = 0; j < 8; j++) {
            float vv = acc[i][j];
            if (EPI & 2) vv += bias[nBase + tn + j];
            if (EPI & 4) vv = 0.5f * vv * (1.0f + erff(vv * 0.70710678118654752f));
            if (EPI & 1) vv += cinrow[j];
            crow[j] = vv;
        }
    }
}

// ---------------- host launcher ----------------
extern "C" void kernel_launch(void* const* d_in, const int* in_sizes, int n_in,
                              void* d_out, int out_size) {
    const int*   x    = (const int*)  d_in[0];
    const float* emb  = (const float*)d_in[1];
    const float* Wq   = (const float*)d_in[2];
    const float* Wk   = (const float*)d_in[3];
    const float* Wv   = (const float*)d_in[4];
    const float* Wo   = (const float*)d_in[5];
    const float* ln1w = (const float*)d_in[6];
    const float* ln1b = (const float*)d_in[7];
    const float* W1   = (const float*)d_in[8];
    const float* b1   = (const float*)d_in[9];
    const float* W2   = (const float*)d_in[10];
    const float* b2   = (const float*)d_in[11];
    const float* ln2w = (const float*)d_in[12];
    const float* ln2b = (const float*)d_in[13];
    const float* Wout = (const float*)d_in[14];
    const float* bout = (const float*)d_in[15];
    (void)in_sizes; (void)n_in;

    float* out = (float*)d_out;

    void* p;
    cudaGetSymbolAddress(&p, g_h);   float* h   = (float*)p;
    cudaGetSymbolAddress(&p, g_lnb); float* lnb = (float*)p;
    cudaGetSymbolAddress(&p, g_q);   float* qb  = (float*)p;
    cudaGetSymbolAddress(&p, g_k);   float* kb  = (float*)p;
    cudaGetSymbolAddress(&p, g_v);   float* vb  = (float*)p;
    cudaGetSymbolAddress(&p, g_o);   float* ob  = (float*)p;
    cudaGetSymbolAddress(&p, g_mid); float* mid = (float*)p;

    float* ents;
    if ((long long)out_size >= (LOGITS_ELEMS + ENTS_ELEMS)) {
        ents = out + LOGITS_ELEMS;
    } else {
        cudaGetSymbolAddress(&p, g_ents_scratch);
        ents = (float*)p;
    }

    cudaFuncSetAttribute(attn_kernel, cudaFuncAttributeMaxDynamicSharedMemorySize, ATTN_SMEM);

    const dim3 gD(DM / BNt,    T_TOK / BMt);   // (8, 16)
    const dim3 gF(FF / BNt,    T_TOK / BMt);   // (32, 16)
    const dim3 gV(VOCAB / BNt, T_TOK / BMt);   // (250, 16)

    rope_table_kernel<<<16, 256>>>();
    embed_kernel<<<T_TOK, 256>>>(x, emb, h);

    int step = 0;
    auto run_layer = [&](int L) {
        const size_t offD  = (size_t)L * DM * DM;
        const size_t offFF = (size_t)L * FF * DM;
        // LN1
        ln_kernel<<<T_TOK, 256>>>(h, ln1w + (size_t)L * DM, ln1b + (size_t)L * DM, lnb);
        // QKV projections
        sgemm_nt<0><<<gD, 256>>>(lnb, Wq + offD, nullptr, nullptr, qb, T_TOK, DM, DM);
        sgemm_nt<0><<<gD, 256>>>(lnb, Wk + offD, nullptr, nullptr, kb, T_TOK, DM, DM);
        sgemm_nt<0><<<gD, 256>>>(lnb, Wv + offD, nullptr, nullptr, vb, T_TOK, DM, DM);
        // RoPE on q, k
        rope_apply_kernel<<<(T_TOK * NH * 32 + 255) / 256, 256>>>(qb);
        rope_apply_kernel<<<(T_TOK * NH * 32 + 255) / 256, 256>>>(kb);
        // fused attention + entropy
        attn_kernel<<<16 * NH, 128, ATTN_SMEM>>>(qb, kb, vb, ob,
                                                 ents + (size_t)step * T_TOK * NH);
        // x = x + o @ Wo^T (residual fused, in-place on h)
        sgemm_nt<1><<<gD, 256>>>(ob, Wo + offD, nullptr, h, h, T_TOK, DM, DM);
        // LN2
        ln_kernel<<<T_TOK, 256>>>(h, ln2w + (size_t)L * DM, ln2b + (size_t)L * DM, lnb);
        // mid = gelu(lnb @ W1^T + b1)
        sgemm_nt<6><<<gF, 256>>>(lnb, W1 + offFF, b1 + (size_t)L * FF, nullptr, mid,
                                 T_TOK, FF, DM);
        // x = x + (mid @ W2^T + b2)  (in-place on h)
        sgemm_nt<3><<<gD, 256>>>(mid, W2 + offFF, b2 + (size_t)L * DM, h, h,
                                 T_TOK, DM, FF);
        step++;
    };

    // MAX_LOOPS=3 over layers 0..2, then layers 3..5 once
    for (int loop = 0; loop < 3; loop++)
        for (int L = 0; L < 3; L++) run_layer(L);
    for (int L = 3; L < 6; L++) run_layer(L);

    // logits = h @ Wout^T + bout
    sgemm_nt<2><<<gV, 256>>>(h, Wout, bout, nullptr, out, T_TOK, VOCAB, DM);
}

// round 2
// speedup vs baseline: 1.0022x; 1.0022x over previous
#include <cuda_runtime.h>
#include <math.h>

// ---------------- problem constants ----------------
#define T_TOK   2048        // B*S
#define DM      1024
#define NH      16
#define HD      64
#define FF      4096
#define VOCAB   32000
#define SEQL    128
#define NSTEPS  12
#define LOGITS_ELEMS 65536000LL   // 2048*32000
#define ENTS_ELEMS   393216LL     // 12*2048*16

// ---------------- device scratch (no cudaMalloc allowed) ----------------
__device__ float g_h  [T_TOK*DM];
__device__ float g_lnb[T_TOK*DM];
__device__ float g_q  [T_TOK*DM];
__device__ float g_k  [T_TOK*DM];
__device__ float g_v  [T_TOK*DM];
__device__ float g_o  [T_TOK*DM];
__device__ float g_mid[T_TOK*FF];
__device__ float g_ents_scratch[NSTEPS*T_TOK*NH];
__device__ float g_cos[SEQL*32];
__device__ float g_sin[SEQL*32];

// ---------------- RoPE table ----------------
__global__ void rope_table_kernel() {
    int i = blockIdx.x * blockDim.x + threadIdx.x;
    if (i >= SEQL * 32) return;
    int s = i >> 5;
    int j = i & 31;
    // inv = 10000^(-(2j)/64)
    float inv = expf(-((2.0f * j) / 64.0f) * 9.210340371976184f); // ln(10000)
    float f = (float)s * inv;
    g_cos[i] = cosf(f);
    g_sin[i] = sinf(f);
}

// ---------------- embedding gather ----------------
__global__ void embed_kernel(const int* __restrict__ x,
                             const float* __restrict__ emb,
                             float* __restrict__ h) {
    int i = blockIdx.x * blockDim.x + threadIdx.x;     // float4 units
    if (i >= T_TOK * (DM / 4)) return;
    int row = i >> 8;               // DM/4 = 256
    int col = i & 255;
    int tok = x[row];
    reinterpret_cast<float4*>(h)[(size_t)row * 256 + col] =
        reinterpret_cast<const float4*>(emb)[(size_t)tok * 256 + col];
}

// ---------------- LayerNorm (one block per token) ----------------
__global__ void ln_kernel(const float* __restrict__ x,
                          const float* __restrict__ w,
                          const float* __restrict__ b,
                          float* __restrict__ y) {
    int t = blockIdx.x;
    int tid = threadIdx.x;
    const float4* xr = reinterpret_cast<const float4*>(x + (size_t)t * DM);
    float4 v = xr[tid];
    float s  = v.x + v.y + v.z + v.w;
    float sq = v.x*v.x + v.y*v.y + v.z*v.z + v.w*v.w;
    #pragma unroll
    for (int o = 16; o > 0; o >>= 1) {
        s  += __shfl_down_sync(0xFFFFFFFFu, s,  o);
        sq += __shfl_down_sync(0xFFFFFFFFu, sq, o);
    }
    __shared__ float ss[8], sqs[8];
    __shared__ float s_mean, s_rstd;
    int wid = tid >> 5, lane = tid & 31;
    if (lane == 0) { ss[wid] = s; sqs[wid] = sq; }
    __syncthreads();
    if (tid == 0) {
        float S = 0.f, Q = 0.f;
        #pragma unroll
        for (int i = 0; i < 8; i++) { S += ss[i]; Q += sqs[i]; }
        float m = S * (1.0f / DM);
        float var = Q * (1.0f / DM) - m * m;
        s_mean = m;
        s_rstd = rsqrtf(var + 1e-5f);
    }
    __syncthreads();
    float m = s_mean, r = s_rstd;
    float4 wv = reinterpret_cast<const float4*>(w)[tid];
    float4 bv = reinterpret_cast<const float4*>(b)[tid];
    float4 out;
    out.x = (v.x - m) * r * wv.x + bv.x;
    out.y = (v.y - m) * r * wv.y + bv.y;
    out.z = (v.z - m) * r * wv.z + bv.z;
    out.w = (v.w - m) * r * wv.w + bv.w;
    reinterpret_cast<float4*>(y + (size_t)t * DM)[tid] = out;
}

// ---------------- RoPE apply (in-place) ----------------
__global__ void rope_apply_kernel(float* __restrict__ x) {
    int i = blockIdx.x * blockDim.x + threadIdx.x;   // pair index
    if (i >= T_TOK * NH * 32) return;
    int t   = i >> 9;          // NH*32 = 512
    int rem = i & 511;
    int h   = rem >> 5;
    int j   = rem & 31;
    int s   = t & (SEQL - 1);
    float c  = g_cos[s * 32 + j];
    float sn = g_sin[s * 32 + j];
    size_t base = (size_t)t * DM + h * HD + 2 * j;
    float xr = x[base], xi = x[base + 1];
    x[base]     = xr * c - xi * sn;
    x[base + 1] = xr * sn + xi * c;
}

// ---------------- fused attention + entropy (one block per (b,h)) ----------------
#define ATTN_SMEM ((8192 + 8192 + 128*129) * 4)
__global__ void __launch_bounds__(128) attn_kernel(
    const float* __restrict__ q, const float* __restrict__ k,
    const float* __restrict__ v, float* __restrict__ o,
    float* __restrict__ ent) {
    extern __shared__ float sm[];
    float* Ks = sm;                 // 128 x 64
    float* Vs = sm + 8192;          // 128 x 64
    float* Sc = sm + 16384;         // 128 x 129 (padded)
    int bh = blockIdx.x;
    int b = bh >> 4, h = bh & 15;
    size_t rowbase = (size_t)(b * SEQL) * DM + h * HD;
    int tid = threadIdx.x;

    // cooperative load of K, V tiles (float4 units: 128 rows * 16)
    for (int i = tid; i < 2048; i += 128) {
        int r = i >> 4;
        int c = (i & 15) << 2;
        *reinterpret_cast<float4*>(&Ks[r * 64 + c]) =
            *reinterpret_cast<const float4*>(k + rowbase + (size_t)r * DM + c);
        *reinterpret_cast<float4*>(&Vs[r * 64 + c]) =
            *reinterpret_cast<const float4*>(v + rowbase + (size_t)r * DM + c);
    }
    // per-thread query row
    float qr[64];
    const float* qp = q + rowbase + (size_t)tid * DM;
    #pragma unroll
    for (int c = 0; c < 64; c += 4) {
        float4 t4 = *reinterpret_cast<const float4*>(qp + c);
        qr[c] = t4.x; qr[c+1] = t4.y; qr[c+2] = t4.z; qr[c+3] = t4.w;
    }
    __syncthreads();

    float* srow = &Sc[tid * 129];
    float mx = -1e30f;
    for (int kk = 0; kk < 128; kk++) {
        float d = 0.f;
        const float* krow = &Ks[kk * 64];
        #pragma unroll
        for (int c = 0; c < 64; c++) d += qr[c] * krow[c];
        d *= 0.125f;                      // HEAD_DIM^-0.5
        srow[kk] = d;
        mx = fmaxf(mx, d);
    }
    float l = 0.f, s1 = 0.f;
    for (int kk = 0; kk < 128; kk++) {
        float sv = srow[kk] - mx;
        float e = expf(sv);
        l  += e;
        s1 += e * sv;
        srow[kk] = e;
    }
    float invl = 1.0f / l;
    // ent = (log(l) - s1/l) * log2(e)
    ent[(size_t)(b * SEQL + tid) * NH + h] = (logf(l) - s1 * invl) * 1.44269504f;

    float acc[64];
    #pragma unroll
    for (int c = 0; c < 64; c++) acc[c] = 0.f;
    for (int kk = 0; kk < 128; kk++) {
        float p = srow[kk];
        const float* vrow = &Vs[kk * 64];
        #pragma unroll
        for (int c = 0; c < 64; c++) acc[c] += p * vrow[c];
    }
    float* op = o + rowbase + (size_t)tid * DM;
    #pragma unroll
    for (int c = 0; c < 64; c += 4) {
        float4 t4 = make_float4(acc[c]*invl, acc[c+1]*invl, acc[c+2]*invl, acc[c+3]*invl);
        *reinterpret_cast<float4*>(op + c) = t4;
    }
}

// ---------------- tiled fp32 NT GEMM: C[M,N] = A[M,K] * B[N,K]^T (+epilogue) ----------------
// EPI flags: 1 = +Cin residual, 2 = +bias, 4 = exact GELU (after bias, before residual)
#define BMt 128
#define BNt 128
#define BKt 16
template<int EPI>
__global__ void __launch_bounds__(256) sgemm_nt(
    const float* __restrict__ A, const float* __restrict__ B,
    const float* __restrict__ bias, const float* __restrict__ Cin,
    float* __restrict__ C, int M, int N, int K) {
    __shared__ float As[BKt][BMt + 4];
    __shared__ float Bs[BKt][BNt + 4];
    const int tid = threadIdx.x;
    const int tm = (tid >> 4) << 3;
    const int tn = (tid & 15) << 3;
    const int mBase = blockIdx.y * BMt;
    const int nBase = blockIdx.x * BNt;
    const float* Ab = A + (size_t)mBase * K;
    const float* Bb = B + (size_t)nBase * K;

    float acc[8][8];
    #pragma unroll
    for (int i = 0; i < 8; i++)
        #pragma unroll
        for (int j = 0; j < 8; j++) acc[i][j] = 0.f;

    const int lr = tid >> 2;          // 0..63
    const int lc = (tid & 3) << 2;    // 0,4,8,12

    for (int kt = 0; kt < K; kt += BKt) {
        #pragma unroll
        for (int half = 0; half < 2; half++) {
            int r = lr + 64 * half;
            float4 a = *reinterpret_cast<const float4*>(Ab + (size_t)r * K + kt + lc);
            As[lc + 0][r] = a.x; As[lc + 1][r] = a.y;
            As[lc + 2][r] = a.z; As[lc + 3][r] = a.w;
            float4 bv = *reinterpret_cast<const float4*>(Bb + (size_t)r * K + kt + lc);
            Bs[lc + 0][r] = bv.x; Bs[lc + 1][r] = bv.y;
            Bs[lc + 2][r] = bv.z; Bs[lc + 3][r] = bv.w;
        }
        __syncthreads();
        #pragma unroll
        for (int kk = 0; kk < BKt; kk++) {
            float ra[8], rb[8];
            #pragma unroll
            for (int i = 0; i < 8; i++) ra[i] = As[kk][tm + i];
            #pragma unroll
            for (int j = 0; j < 8; j++) rb[j] = Bs[kk][tn + j];
            #pragma unroll
            for (int i = 0; i < 8; i++)
                #pragma unroll
                for (int j = 0; j < 8; j++)
                    acc[i][j] += ra[i] * rb[j];
        }
        __syncthreads();
    }

    #pragma unroll
    for (int i = 0; i < 8; i++) {
        size_t row = (size_t)(mBase + tm + i);
        float* crow = C + row * N + nBase + tn;
        const float* cinrow = (EPI & 1) ? (Cin + row * N + nBase + tn) : nullptr;
        #pragma unroll
        for (int j = 0; j < 8; j++) {
            float vv = acc[i][j];
            if (EPI & 2) vv += bias[nBase + tn + j];
            if (EPI & 4) vv = 0.5f * vv * (1.0f + erff(vv * 0.70710678118654752f));
            if (EPI & 1) vv += cinrow[j];
            crow[j] = vv;
        }
    }
}

// ---------------- host launcher ----------------
extern "C" void kernel_launch(void* const* d_in, const int* in_sizes, int n_in,
                              void* d_out, int out_size) {
    const int*   x    = (const int*)  d_in[0];
    const float* emb  = (const float*)d_in[1];
    const float* Wq   = (const float*)d_in[2];
    const float* Wk   = (const float*)d_in[3];
    const float* Wv   = (const float*)d_in[4];
    const float* Wo   = (const float*)d_in[5];
    const float* ln1w = (const float*)d_in[6];
    const float* ln1b = (const float*)d_in[7];
    const float* W1   = (const float*)d_in[8];
    const float* b1   = (const float*)d_in[9];
    const float* W2   = (const float*)d_in[10];
    const float* b2   = (const float*)d_in[11];
    const float* ln2w = (const float*)d_in[12];
    const float* ln2b = (const float*)d_in[13];
    const float* Wout = (const float*)d_in[14];
    const float* bout = (const float*)d_in[15];
    (void)in_sizes; (void)n_in;

    float* out = (float*)d_out;

    void* p;
    cudaGetSymbolAddress(&p, g_h);   float* h   = (float*)p;
    cudaGetSymbolAddress(&p, g_lnb); float* lnb = (float*)p;
    cudaGetSymbolAddress(&p, g_q);   float* qb  = (float*)p;
    cudaGetSymbolAddress(&p, g_k);   float* kb  = (float*)p;
    cudaGetSymbolAddress(&p, g_v);   float* vb  = (float*)p;
    cudaGetSymbolAddress(&p, g_o);   float* ob  = (float*)p;
    cudaGetSymbolAddress(&p, g_mid); float* mid = (float*)p;

    float* ents;
    if ((long long)out_size >= (LOGITS_ELEMS + ENTS_ELEMS)) {
        ents = out + LOGITS_ELEMS;
    } else {
        cudaGetSymbolAddress(&p, g_ents_scratch);
        ents = (float*)p;
    }

    cudaFuncSetAttribute(attn_kernel, cudaFuncAttributeMaxDynamicSharedMemorySize, ATTN_SMEM);

    const dim3 gD(DM / BNt,    T_TOK / BMt);   // (8, 16)
    const dim3 gF(FF / BNt,    T_TOK / BMt);   // (32, 16)
    const dim3 gV(VOCAB / BNt, T_TOK / BMt);   // (250, 16)

    rope_table_kernel<<<16, 256>>>();
    embed_kernel<<<T_TOK, 256>>>(x, emb, h);

    int step = 0;
    auto run_layer = [&](int L) {
        const size_t offD  = (size_t)L * DM * DM;
        const size_t offFF = (size_t)L * FF * DM;
        // LN1
        ln_kernel<<<T_TOK, 256>>>(h, ln1w + (size_t)L * DM, ln1b + (size_t)L * DM, lnb);
        // QKV projections
        sgemm_nt<0><<<gD, 256>>>(lnb, Wq + offD, nullptr, nullptr, qb, T_TOK, DM, DM);
        sgemm_nt<0><<<gD, 256>>>(lnb, Wk + offD, nullptr, nullptr, kb, T_TOK, DM, DM);
        sgemm_nt<0><<<gD, 256>>>(lnb, Wv + offD, nullptr, nullptr, vb, T_TOK, DM, DM);
        // RoPE on q, k
        rope_apply_kernel<<<(T_TOK * NH * 32 + 255) / 256, 256>>>(qb);
        rope_apply_kernel<<<(T_TOK * NH * 32 + 255) / 256, 256>>>(kb);
        // fused attention + entropy
        attn_kernel<<<16 * NH, 128, ATTN_SMEM>>>(qb, kb, vb, ob,
                                                 ents + (size_t)step * T_TOK * NH);
        // x = x + o @ Wo^T (residual fused, in-place on h)
        sgemm_nt<1><<<gD, 256>>>(ob, Wo + offD, nullptr, h, h, T_TOK, DM, DM);
        // LN2
        ln_kernel<<<T_TOK, 256>>>(h, ln2w + (size_t)L * DM, ln2b + (size_t)L * DM, lnb);
        // mid = gelu(lnb @ W1^T + b1)
        sgemm_nt<6><<<gF, 256>>>(lnb, W1 + offFF, b1 + (size_t)L * FF, nullptr, mid,
                                 T_TOK, FF, DM);
        // x = x + (mid @ W2^T + b2)  (in-place on h)
        sgemm_nt<3><<<gD, 256>>>(mid, W2 + offFF, b2 + (size_t)L * DM, h, h,
                                 T_TOK, DM, FF);
        step++;
    };

    // MAX_LOOPS=3 over layers 0..2, then layers 3..5 once
    for (int loop = 0; loop < 3; loop++)
        for (int L = 0; L < 3; L++) run_layer(L);
    for (int L = 3; L < 6; L++) run_layer(L);

    // logits = h @ Wout^T + bout
    sgemm_nt<2><<<gV, 256>>>(h, Wout, bout, nullptr, out, T_TOK, VOCAB, DM);
}